// round 13
// baseline (speedup 1.0000x reference)
#include <cuda_runtime.h>
#include <cuda_bf16.h>
#include <cstdint>

// Problem constants
#define BB 4
#define FF 128        // feature = hidden size
#define TT 32000
#define KK 32
#define HH 64
#define GG 384        // 3*FF
#define BT (BB*TT)    // 128000

#define NBLK 1000     // 32-step blocks over T
#define NCHUNK 18     // time chunks per (b,dir) -> 144 CTAs
#define WARMB 16      // warmup blocks (512 steps); measured lambda ~0.95/step

// ---------------- scratch (static device globals; allocation-free) ----------------
__device__ __nv_bfloat16 g_shi[(size_t)BT * FF];  // conv out, bf16 hi (32.8 MB)
__device__ __nv_bfloat16 g_slo[(size_t)BT * FF];  // conv out, bf16 lo
__device__ float g_X[(size_t)2 * BT * GG];        // [dir][b*T+t][g] (393 MB)
__device__ __nv_bfloat16 g_Whi[2][GG][FF];        // W_ih bf16 hi
__device__ __nv_bfloat16 g_Wlo[2][GG][FF];        // W_ih bf16 lo

// ---------------- generic helpers ----------------
__device__ __forceinline__ unsigned long long ffma2(unsigned long long a,
                                                    unsigned long long b,
                                                    unsigned long long c) {
    unsigned long long d;
    asm("fma.rn.f32x2 %0, %1, %2, %3;" : "=l"(d) : "l"(a), "l"(b), "l"(c));
    return d;
}
__device__ __forceinline__ unsigned long long fadd2(unsigned long long a,
                                                    unsigned long long b) {
    unsigned long long d;
    asm("add.rn.f32x2 %0, %1, %2;" : "=l"(d) : "l"(a), "l"(b));
    return d;
}
__device__ __forceinline__ float lo32(unsigned long long v) {
    return __uint_as_float((unsigned)(v & 0xffffffffull));
}
__device__ __forceinline__ float hi32(unsigned long long v) {
    return __uint_as_float((unsigned)(v >> 32));
}
__device__ __forceinline__ float fsig(float x) {
    return __fdividef(1.f, 1.f + __expf(-x));   // overflow-safe: inf -> 0
}
__device__ __forceinline__ float ftanh_(float x) {
    x = fminf(fmaxf(x, -15.f), 15.f);   // clamp: avoids exp overflow -> NaN
    float e = __expf(-2.f * x);
    return __fdividef(1.f - e, 1.f + e);
}
__device__ __forceinline__ void mma16816(float* c, const unsigned* a,
                                         const unsigned* b) {
    asm volatile(
        "mma.sync.aligned.m16n8k16.row.col.f32.bf16.bf16.f32 "
        "{%0,%1,%2,%3}, {%4,%5,%6,%7}, {%8,%9}, {%0,%1,%2,%3};"
        : "+f"(c[0]), "+f"(c[1]), "+f"(c[2]), "+f"(c[3])
        : "r"(a[0]), "r"(a[1]), "r"(a[2]), "r"(a[3]), "r"(b[0]), "r"(b[1]));
}

// ---------------- kernel 1: causal FIR conv + PReLU -> bf16 hi/lo ----------------
#define CT2 2048
__global__ __launch_bounds__(256) void conv_prelu_kernel(
    const float* __restrict__ x, const float* __restrict__ kern,
    const float* __restrict__ kw, const float* __restrict__ pa) {
    __shared__ float keff_s[KK];
    __shared__ __align__(16) float xs[CT2 + 48];
    int bf = blockIdx.x;            // 0..511
    int b = bf >> 7, f = bf & 127;
    const float* xrow = x + (size_t)bf * TT;   // x layout [B,F,T]
    float a = *pa;

    if (threadIdx.x < KK) {
        float s = 0.f;
        #pragma unroll 8
        for (int h = 0; h < HH; h++)
            s += kern[h * KK + threadIdx.x] * kw[h * KK + threadIdx.x];
        keff_s[threadIdx.x] = s;
    }
    __syncthreads();
    float kr[KK];
    #pragma unroll
    for (int j = 0; j < KK; j++) kr[j] = keff_s[j];

    for (int t0 = 0; t0 < TT; t0 += CT2) {
        for (int i = threadIdx.x; i < CT2 + 40; i += 256) {
            int tt = t0 - (KK - 1) + i;
            xs[i] = ((unsigned)tt < (unsigned)TT) ? xrow[tt] : 0.f;
        }
        __syncthreads();
        int tb = threadIdx.x * 8;         // local base, 0..2040
        int t = t0 + tb;
        if (t < TT) {
            float win[40];
            #pragma unroll
            for (int q = 0; q < 10; q++)
                *(float4*)(win + 4 * q) = *(const float4*)(xs + tb + 4 * q);
            float acc[8];
            #pragma unroll
            for (int u = 0; u < 8; u++) acc[u] = 0.f;
            #pragma unroll
            for (int j = 0; j < KK; j++)
                #pragma unroll
                for (int u = 0; u < 8; u++)
                    acc[u] += kr[j] * win[31 + u - j];
            #pragma unroll
            for (int u = 0; u < 8; u++) {
                if (t + u < TT) {
                    float v = acc[u];
                    v = (v >= 0.f) ? v : a * v;
                    size_t idx = (size_t)(b * TT + t + u) * FF + f;
                    __nv_bfloat16 hb = __float2bfloat16(v);
                    g_shi[idx] = hb;
                    g_slo[idx] = __float2bfloat16(v - __bfloat162float(hb));
                }
            }
        }
        __syncthreads();
    }
}

// ---------------- kernel 1b: W_ih fp32 -> bf16 hi/lo ----------------
__global__ __launch_bounds__(256) void convW_kernel(
    const float* __restrict__ Wf, const float* __restrict__ Wb) {
    int row = blockIdx.x * 256 + threadIdx.x;   // 0..767
    if (row >= 2 * GG) return;
    int dir = row >= GG, n = row - dir * GG;
    const float* src = (dir ? Wb : Wf) + (size_t)n * FF;
    #pragma unroll 4
    for (int c = 0; c < FF; c++) {
        float v = src[c];
        __nv_bfloat16 h = __float2bfloat16(v);
        float l = v - __bfloat162float(h);
        g_Whi[dir][n][c] = h;
        g_Wlo[dir][n][c] = __float2bfloat16(l);
    }
}

// ---------------- kernel 2: X = seq @ W_ih^T + b_ih via mma.sync bf16 split ----------------
// grid (8, 1000): x = dir*4 + ntile (fastest -> same-m CTAs co-resident, A hits L2).
// CTA: 128 threads = 4 warps (2m x 2n), tile M=128 x N=96. Warp: m64 x n48 ->
// 4x6 m16n8 accum frags. Fragments LDG'd directly from global bf16 hi/lo.
// 3 products accumulated into the same fp32 accums: hi*hi + hi*lo + lo*hi.
__global__ __launch_bounds__(128) void gemm_mma_kernel(
    const float* __restrict__ bf_, const float* __restrict__ bb_) {
    int xx = blockIdx.x;                 // 0..7
    int dir = xx >> 2, nt = xx & 3;
    size_t m0 = (size_t)blockIdx.y * 128;
    int n0 = nt * 96;
    int tid = threadIdx.x, wid = tid >> 5, lane = tid & 31;
    int g = lane >> 2, tg = lane & 3;
    int wm = wid >> 1, wn = wid & 1;
    int mbase = wm * 64;
    int nbase = n0 + wn * 48;
    const float* bias = dir ? bb_ : bf_;
    const __nv_bfloat16* Whi = &g_Whi[dir][0][0];
    const __nv_bfloat16* Wlo = &g_Wlo[dir][0][0];

    float acc[4][6][4];
    #pragma unroll
    for (int i = 0; i < 4; i++)
        #pragma unroll
        for (int j = 0; j < 6; j++)
            #pragma unroll
            for (int q = 0; q < 4; q++) acc[i][j][q] = 0.f;

    #pragma unroll 2
    for (int k16 = 0; k16 < 8; k16++) {
        int k0 = k16 * 16;
        // A fragments: rows mbase+fm*16+{g, g+8}, k pairs {tg*2, tg*2+8}
        unsigned ah[4][4], al[4][4];
        #pragma unroll
        for (int fm = 0; fm < 4; fm++) {
            size_t r = m0 + mbase + fm * 16 + g;
            const unsigned* ph = (const unsigned*)(g_shi + r * FF + k0 + tg * 2);
            const unsigned* pl = (const unsigned*)(g_slo + r * FF + k0 + tg * 2);
            ah[fm][0] = ph[0];       ah[fm][1] = ph[8 * 64];
            ah[fm][2] = ph[4];       ah[fm][3] = ph[8 * 64 + 4];
            al[fm][0] = pl[0];       al[fm][1] = pl[8 * 64];
            al[fm][2] = pl[4];       al[fm][3] = pl[8 * 64 + 4];
        }
        // B fragments: n = nbase+fn*8+g, k pairs {tg*2, tg*2+8}
        unsigned bh[6][2], bl[6][2];
        #pragma unroll
        for (int fn = 0; fn < 6; fn++) {
            size_t n = (size_t)(nbase + fn * 8 + g);
            const unsigned* qh = (const unsigned*)(Whi + n * FF + k0 + tg * 2);
            const unsigned* ql = (const unsigned*)(Wlo + n * FF + k0 + tg * 2);
            bh[fn][0] = qh[0]; bh[fn][1] = qh[4];
            bl[fn][0] = ql[0]; bl[fn][1] = ql[4];
        }
        #pragma unroll
        for (int fm = 0; fm < 4; fm++)
            #pragma unroll
            for (int fn = 0; fn < 6; fn++) {
                mma16816(acc[fm][fn], ah[fm], bh[fn]);
                mma16816(acc[fm][fn], ah[fm], bl[fn]);
                mma16816(acc[fm][fn], al[fm], bh[fn]);
            }
    }

    // epilogue: c0,c1 -> (row, n..n+1); c2,c3 -> (row+8, n..n+1)
    #pragma unroll
    for (int fm = 0; fm < 4; fm++) {
        size_t r = m0 + mbase + fm * 16 + g;
        float* row0 = g_X + ((size_t)dir * BT + r) * GG;
        float* row8 = row0 + (size_t)8 * GG;
        #pragma unroll
        for (int fn = 0; fn < 6; fn++) {
            int n = nbase + fn * 8 + tg * 2;
            float b0 = __ldg(bias + n), b1 = __ldg(bias + n + 1);
            *(float2*)(row0 + n) =
                make_float2(acc[fm][fn][0] + b0, acc[fm][fn][1] + b1);
            *(float2*)(row8 + n) =
                make_float2(acc[fm][fn][2] + b0, acc[fm][fn][3] + b1);
        }
    }
}

// ---------------- kernel 3: time-parallel chunked recurrence ----------------
// 144 CTAs = 18 chunks x (4 batches x 2 dirs), 384 threads each.
__global__ __launch_bounds__(384, 1) void gru_kernel(
    const float* __restrict__ Whh_f, const float* __restrict__ bhh_f,
    const float* __restrict__ Whh_b, const float* __restrict__ bhh_b,
    float* __restrict__ out) {
    __shared__ __align__(16) float hs[128];   // h state
    __shared__ float gate[256];               // sigmoid(r), sigmoid(z)
    __shared__ float h_buf[128][33];          // 32-step output ring (+pad)

    int cta = blockIdx.x;                     // 0..143
    int c   = cta >> 3;                       // chunk 0..17
    int dir = cta & 1;
    int b   = (cta >> 1) & 3;
    const float* Whh = dir ? Whh_b : Whh_f;
    int g = threadIdx.x;
    int wid = g >> 5, lane = g & 31;
    float bh = (dir ? bhh_b : bhh_f)[g];

    // chunk block range: 1000 = 10*56 + 8*55
    int B0 = c * 55 + (c < 10 ? c : 10);
    int B1 = B0 + 55 + (c < 10 ? 1 : 0);
    int loBlk, nBlk;
    if (!dir) {
        int p = B0 - WARMB; if (p < 0) p = 0;
        loBlk = p; nBlk = B1 - p;
    } else {
        int p = B1 + WARMB; if (p > NBLK) p = NBLK;
        loBlk = B0; nBlk = p - B0;
    }
    int blk0 = dir ? (loBlk + nBlk - 1) : loBlk;   // first processed block
    int sgn  = dir ? -1 : 1;
    int tfirst = dir ? (32 * blk0 + 31) : (32 * blk0);

    unsigned long long w[64];
    {
        const unsigned long long* wrow =
            (const unsigned long long*)(Whh + (size_t)g * FF);
        #pragma unroll
        for (int k = 0; k < 64; k++) w[k] = wrow[k];
    }

    const float* Xseq = g_X + ((size_t)dir * BB + b) * (size_t)TT * GG;
    const float* xp = Xseq + (size_t)tfirst * GG + g;
    ptrdiff_t stepX = dir ? -(ptrdiff_t)GG : (ptrdiff_t)GG;
    float* obase = out + (size_t)b * FF * TT;

    if (g < 128) hs[g] = 0.f;
    __syncthreads();

    float h_reg = 0.f;
    float xt = __ldg(xp); xp += stepX;
    float x1 = __ldg(xp); xp += stepX;
    int tpre = tfirst + 2 * sgn;          // t index xp currently points at

    const ulonglong2* hv2 = (const ulonglong2*)hs;

    #pragma unroll 1
    for (int ib = 0; ib < nBlk; ib++) {
        int blk = dir ? (blk0 - ib) : (blk0 + ib);
        #pragma unroll 2
        for (int s = 0; s < 32; s++) {
            float x2 = 0.f;
            if ((unsigned)tpre < (unsigned)TT) x2 = __ldg(xp);
            xp += stepX; tpre += sgn;

            unsigned long long a0 = 0, a1 = 0, a2 = 0, a3 = 0;
            #pragma unroll
            for (int k = 0; k < 32; k += 2) {
                ulonglong2 p = hv2[k];
                ulonglong2 q = hv2[k + 1];
                a0 = ffma2(w[2 * k + 0], p.x, a0);
                a1 = ffma2(w[2 * k + 1], p.y, a1);
                a2 = ffma2(w[2 * k + 2], q.x, a2);
                a3 = ffma2(w[2 * k + 3], q.y, a3);
            }
            a0 = fadd2(a0, a1); a2 = fadd2(a2, a3); a0 = fadd2(a0, a2);
            float pre = lo32(a0) + hi32(a0) + bh;

            if (g < 256) gate[g] = fsig(xt + pre);   // r (g<128) / z (128..255)
            __syncthreads();                          // BAR1
            if (g >= 256) {
                int j = g - 256;
                float r = gate[j];
                float z = gate[128 + j];
                float n = ftanh_(xt + r * pre);      // pre == gn for this row
                h_reg = n + z * (h_reg - n);         // (1-z)*n + z*h
                hs[j] = h_reg;
                h_buf[j][s] = h_reg;
            }
            __syncthreads();                          // BAR2
            xt = x1; x1 = x2;
        }

        bool core = dir ? (blk < B1) : (blk >= B0);
        if (core) {
            int tb = dir ? (32 * blk + 31) : (32 * blk);
            for (int f = wid; f < 128; f += 12) {
                float v = h_buf[f][lane];
                atomicAdd(obase + (size_t)f * TT + tb + sgn * lane, v);
            }
        }
    }
}

// ---------------- launch ----------------
extern "C" void kernel_launch(void* const* d_in, const int* in_sizes, int n_in,
                              void* d_out, int out_size) {
    const float* x    = (const float*)d_in[0];
    const float* kern = (const float*)d_in[1];
    const float* kw   = (const float*)d_in[2];
    const float* pa   = (const float*)d_in[3];
    const float* Wihf = (const float*)d_in[4];
    const float* Whhf = (const float*)d_in[5];
    const float* bihf = (const float*)d_in[6];
    const float* bhhf = (const float*)d_in[7];
    const float* Wihb = (const float*)d_in[8];
    const float* Whhb = (const float*)d_in[9];
    const float* bihb = (const float*)d_in[10];
    const float* bhhb = (const float*)d_in[11];
    float* out = (float*)d_out;

    cudaMemsetAsync(out, 0, (size_t)out_size * sizeof(float));
    conv_prelu_kernel<<<BB * FF, 256>>>(x, kern, kw, pa);
    convW_kernel<<<3, 256>>>(Wihf, Wihb);
    gemm_mma_kernel<<<dim3(8, 1000), 128>>>(bihf, bihb);
    gru_kernel<<<NCHUNK * 2 * BB, 384>>>(Whhf, bhhf, Whhb, bhhb, out);
}

// round 17
// speedup vs baseline: 1.0901x; 1.0901x over previous
#include <cuda_runtime.h>
#include <cuda_bf16.h>
#include <cstdint>

// Problem constants
#define BB 4
#define FF 128        // feature = hidden size
#define TT 32000
#define KK 32
#define HH 64
#define GG 384        // 3*FF
#define BT (BB*TT)    // 128000

#define NBLK 1000     // 32-step blocks over T
#define NCHUNK 18     // time chunks per (b,dir) -> 144 CTAs
#define WARMB 16      // warmup blocks (512 steps); measured lambda ~0.95/step

// ---------------- scratch (static device globals; allocation-free) ----------------
__device__ __nv_bfloat16 g_shi[(size_t)BT * FF];  // conv out, bf16 hi (32.8 MB)
__device__ __nv_bfloat16 g_slo[(size_t)BT * FF];  // conv out, bf16 lo
__device__ float g_X[(size_t)2 * BT * GG];        // [dir][b*T+t][g] (393 MB)
__device__ __nv_bfloat16 g_Whi[2][GG][FF];        // W_ih bf16 hi
__device__ __nv_bfloat16 g_Wlo[2][GG][FF];        // W_ih bf16 lo

// ---------------- generic helpers ----------------
__device__ __forceinline__ unsigned long long ffma2(unsigned long long a,
                                                    unsigned long long b,
                                                    unsigned long long c) {
    unsigned long long d;
    asm("fma.rn.f32x2 %0, %1, %2, %3;" : "=l"(d) : "l"(a), "l"(b), "l"(c));
    return d;
}
__device__ __forceinline__ unsigned long long fadd2(unsigned long long a,
                                                    unsigned long long b) {
    unsigned long long d;
    asm("add.rn.f32x2 %0, %1, %2;" : "=l"(d) : "l"(a), "l"(b));
    return d;
}
__device__ __forceinline__ float lo32(unsigned long long v) {
    return __uint_as_float((unsigned)(v & 0xffffffffull));
}
__device__ __forceinline__ float hi32(unsigned long long v) {
    return __uint_as_float((unsigned)(v >> 32));
}
__device__ __forceinline__ float fsig(float x) {
    return __fdividef(1.f, 1.f + __expf(-x));   // overflow-safe: inf -> 0
}
__device__ __forceinline__ float ftanh_(float x) {
    x = fminf(fmaxf(x, -15.f), 15.f);   // clamp: avoids exp overflow -> NaN
    float e = __expf(-2.f * x);
    return __fdividef(1.f - e, 1.f + e);
}
__device__ __forceinline__ void mma16816(float* c, const unsigned* a,
                                         const unsigned* b) {
    asm volatile(
        "mma.sync.aligned.m16n8k16.row.col.f32.bf16.bf16.f32 "
        "{%0,%1,%2,%3}, {%4,%5,%6,%7}, {%8,%9}, {%0,%1,%2,%3};"
        : "+f"(c[0]), "+f"(c[1]), "+f"(c[2]), "+f"(c[3])
        : "r"(a[0]), "r"(a[1]), "r"(a[2]), "r"(a[3]), "r"(b[0]), "r"(b[1]));
}

// ---------------- kernel 1: causal FIR conv + PReLU -> bf16 hi/lo ----------------
#define CT2 2048
__global__ __launch_bounds__(256) void conv_prelu_kernel(
    const float* __restrict__ x, const float* __restrict__ kern,
    const float* __restrict__ kw, const float* __restrict__ pa) {
    __shared__ float keff_s[KK];
    __shared__ __align__(16) float xs[CT2 + 48];
    int bf = blockIdx.x;            // 0..511
    int b = bf >> 7, f = bf & 127;
    const float* xrow = x + (size_t)bf * TT;   // x layout [B,F,T]
    float a = *pa;

    if (threadIdx.x < KK) {
        float s = 0.f;
        #pragma unroll 8
        for (int h = 0; h < HH; h++)
            s += kern[h * KK + threadIdx.x] * kw[h * KK + threadIdx.x];
        keff_s[threadIdx.x] = s;
    }
    __syncthreads();
    float kr[KK];
    #pragma unroll
    for (int j = 0; j < KK; j++) kr[j] = keff_s[j];

    for (int t0 = 0; t0 < TT; t0 += CT2) {
        for (int i = threadIdx.x; i < CT2 + 40; i += 256) {
            int tt = t0 - (KK - 1) + i;
            xs[i] = ((unsigned)tt < (unsigned)TT) ? xrow[tt] : 0.f;
        }
        __syncthreads();
        int tb = threadIdx.x * 8;         // local base, 0..2040
        int t = t0 + tb;
        if (t < TT) {
            float win[40];
            #pragma unroll
            for (int q = 0; q < 10; q++)
                *(float4*)(win + 4 * q) = *(const float4*)(xs + tb + 4 * q);
            float acc[8];
            #pragma unroll
            for (int u = 0; u < 8; u++) acc[u] = 0.f;
            #pragma unroll
            for (int j = 0; j < KK; j++)
                #pragma unroll
                for (int u = 0; u < 8; u++)
                    acc[u] += kr[j] * win[31 + u - j];
            #pragma unroll
            for (int u = 0; u < 8; u++) {
                if (t + u < TT) {
                    float v = acc[u];
                    v = (v >= 0.f) ? v : a * v;
                    size_t idx = (size_t)(b * TT + t + u) * FF + f;
                    __nv_bfloat16 hb = __float2bfloat16(v);
                    g_shi[idx] = hb;
                    g_slo[idx] = __float2bfloat16(v - __bfloat162float(hb));
                }
            }
        }
        __syncthreads();
    }
}

// ---------------- kernel 1b: W_ih fp32 -> bf16 hi/lo ----------------
__global__ __launch_bounds__(256) void convW_kernel(
    const float* __restrict__ Wf, const float* __restrict__ Wb) {
    int row = blockIdx.x * 256 + threadIdx.x;   // 0..767
    if (row >= 2 * GG) return;
    int dir = row >= GG, n = row - dir * GG;
    const float* src = (dir ? Wb : Wf) + (size_t)n * FF;
    #pragma unroll 4
    for (int c = 0; c < FF; c++) {
        float v = src[c];
        __nv_bfloat16 h = __float2bfloat16(v);
        float l = v - __bfloat162float(h);
        g_Whi[dir][n][c] = h;
        g_Wlo[dir][n][c] = __float2bfloat16(l);
    }
}

// ---------------- kernel 2: X = seq @ W_ih^T + b_ih via mma.sync bf16 split ----------------
// grid 1000 (m-tiles of 128 tokens), 256 threads = 8 warps (2m x 4n).
// A (hi/lo) staged in smem once; 6 iterations (2 dirs x 3 n-tiles of 128):
// stage B (hi/lo) in smem, fragments read via conflict-free LDS.32
// (row stride 136 bf16 = 272B -> bank 4*row+tg, all distinct), 3 bf16
// products accumulated in fp32: hi*hi + hi*lo + lo*hi.
// Each tile row = 128 bf16 = 16 uint4 segments; 128 rows x 16 segs = 2048
// uint4 per matrix -> 8 staging iterations of 256 threads.
#define ASTR 136   // smem row stride in bf16 elements (272B)
__global__ __launch_bounds__(256) void gemm_mma_kernel(
    const float* __restrict__ bf_, const float* __restrict__ bb_) {
    extern __shared__ __align__(16) __nv_bfloat16 sm[];
    __nv_bfloat16* Ah = sm;                    // [128][ASTR]
    __nv_bfloat16* Al = sm + 128 * ASTR;
    __nv_bfloat16* Bh = sm + 2 * 128 * ASTR;
    __nv_bfloat16* Bl = sm + 3 * 128 * ASTR;

    size_t m0 = (size_t)blockIdx.x * 128;
    int tid = threadIdx.x, wid = tid >> 5, lane = tid & 31;
    int g = lane >> 2, tg = lane & 3;
    int wm = wid >> 2, wn = wid & 3;           // 2m x 4n warps
    int mbase = wm * 64;                       // warp m-offset (4 fm frags)
    int nbase = wn * 32;                       // warp n-offset (4 fn frags)

    // ---- stage A hi/lo: 2048 uint4 per matrix, 8 per thread ----
    #pragma unroll
    for (int q = 0; q < 8; q++) {
        int id = q * 256 + tid;                // 0..2047
        int row = id >> 4, seg = id & 15;      // seg: 8 bf16 = 16B
        *(uint4*)(Ah + row * ASTR + seg * 8) =
            *(const uint4*)(g_shi + (m0 + row) * FF + seg * 8);
        *(uint4*)(Al + row * ASTR + seg * 8) =
            *(const uint4*)(g_slo + (m0 + row) * FF + seg * 8);
    }

    #pragma unroll 1
    for (int it = 0; it < 6; it++) {
        int dir = it >= 3;
        int nt = it - dir * 3;
        int n0 = nt * 128;
        const float* bias = dir ? bb_ : bf_;

        if (it > 0) __syncthreads();           // prior iter's B reads done
        // ---- stage B hi/lo for rows n0..n0+127 ----
        #pragma unroll
        for (int q = 0; q < 8; q++) {
            int id = q * 256 + tid;
            int row = id >> 4, seg = id & 15;
            *(uint4*)(Bh + row * ASTR + seg * 8) =
                *(const uint4*)(&g_Whi[dir][n0 + row][seg * 8]);
            *(uint4*)(Bl + row * ASTR + seg * 8) =
                *(const uint4*)(&g_Wlo[dir][n0 + row][seg * 8]);
        }
        __syncthreads();                       // A (it=0) and B visible

        float acc[4][4][4];
        #pragma unroll
        for (int i = 0; i < 4; i++)
            #pragma unroll
            for (int j = 0; j < 4; j++)
                #pragma unroll
                for (int q = 0; q < 4; q++) acc[i][j][q] = 0.f;

        #pragma unroll 2
        for (int k16 = 0; k16 < 8; k16++) {
            int k0 = k16 * 16 + tg * 2;
            unsigned ah[4][4], al[4][4];
            #pragma unroll
            for (int fm = 0; fm < 4; fm++) {
                int r = mbase + fm * 16 + g;
                const __nv_bfloat16* ph = Ah + r * ASTR + k0;
                const __nv_bfloat16* pl = Al + r * ASTR + k0;
                ah[fm][0] = *(const unsigned*)(ph);
                ah[fm][1] = *(const unsigned*)(ph + 8 * ASTR);
                ah[fm][2] = *(const unsigned*)(ph + 8);
                ah[fm][3] = *(const unsigned*)(ph + 8 * ASTR + 8);
                al[fm][0] = *(const unsigned*)(pl);
                al[fm][1] = *(const unsigned*)(pl + 8 * ASTR);
                al[fm][2] = *(const unsigned*)(pl + 8);
                al[fm][3] = *(const unsigned*)(pl + 8 * ASTR + 8);
            }
            unsigned bh[4][2], bl[4][2];
            #pragma unroll
            for (int fn = 0; fn < 4; fn++) {
                int n = nbase + fn * 8 + g;
                const __nv_bfloat16* qh = Bh + n * ASTR + k0;
                const __nv_bfloat16* ql = Bl + n * ASTR + k0;
                bh[fn][0] = *(const unsigned*)(qh);
                bh[fn][1] = *(const unsigned*)(qh + 8);
                bl[fn][0] = *(const unsigned*)(ql);
                bl[fn][1] = *(const unsigned*)(ql + 8);
            }
            #pragma unroll
            for (int fm = 0; fm < 4; fm++)
                #pragma unroll
                for (int fn = 0; fn < 4; fn++) {
                    mma16816(acc[fm][fn], ah[fm], bh[fn]);
                    mma16816(acc[fm][fn], ah[fm], bl[fn]);
                    mma16816(acc[fm][fn], al[fm], bh[fn]);
                }
        }

        // ---- epilogue: c0,c1 -> (row, n..n+1); c2,c3 -> (row+8, ...) ----
        #pragma unroll
        for (int fm = 0; fm < 4; fm++) {
            size_t r = m0 + mbase + fm * 16 + g;
            float* row0 = g_X + ((size_t)dir * BT + r) * GG + n0;
            float* row8 = row0 + (size_t)8 * GG;
            #pragma unroll
            for (int fn = 0; fn < 4; fn++) {
                int n = nbase + fn * 8 + tg * 2;
                float b0 = __ldg(bias + n0 + n), b1 = __ldg(bias + n0 + n + 1);
                *(float2*)(row0 + n) =
                    make_float2(acc[fm][fn][0] + b0, acc[fm][fn][1] + b1);
                *(float2*)(row8 + n) =
                    make_float2(acc[fm][fn][2] + b0, acc[fm][fn][3] + b1);
            }
        }
    }
}

// ---------------- kernel 3: time-parallel chunked recurrence ----------------
// 144 CTAs = 18 chunks x (4 batches x 2 dirs), 384 threads each.
__global__ __launch_bounds__(384, 1) void gru_kernel(
    const float* __restrict__ Whh_f, const float* __restrict__ bhh_f,
    const float* __restrict__ Whh_b, const float* __restrict__ bhh_b,
    float* __restrict__ out) {
    __shared__ __align__(16) float hs[128];   // h state
    __shared__ float gate[256];               // sigmoid(r), sigmoid(z)
    __shared__ float h_buf[128][33];          // 32-step output ring (+pad)

    int cta = blockIdx.x;                     // 0..143
    int c   = cta >> 3;                       // chunk 0..17
    int dir = cta & 1;
    int b   = (cta >> 1) & 3;
    const float* Whh = dir ? Whh_b : Whh_f;
    int g = threadIdx.x;
    int wid = g >> 5, lane = g & 31;
    float bh = (dir ? bhh_b : bhh_f)[g];

    // chunk block range: 1000 = 10*56 + 8*55
    int B0 = c * 55 + (c < 10 ? c : 10);
    int B1 = B0 + 55 + (c < 10 ? 1 : 0);
    int loBlk, nBlk;
    if (!dir) {
        int p = B0 - WARMB; if (p < 0) p = 0;
        loBlk = p; nBlk = B1 - p;
    } else {
        int p = B1 + WARMB; if (p > NBLK) p = NBLK;
        loBlk = B0; nBlk = p - B0;
    }
    int blk0 = dir ? (loBlk + nBlk - 1) : loBlk;   // first processed block
    int sgn  = dir ? -1 : 1;
    int tfirst = dir ? (32 * blk0 + 31) : (32 * blk0);

    unsigned long long w[64];
    {
        const unsigned long long* wrow =
            (const unsigned long long*)(Whh + (size_t)g * FF);
        #pragma unroll
        for (int k = 0; k < 64; k++) w[k] = wrow[k];
    }

    const float* Xseq = g_X + ((size_t)dir * BB + b) * (size_t)TT * GG;
    const float* xp = Xseq + (size_t)tfirst * GG + g;
    ptrdiff_t stepX = dir ? -(ptrdiff_t)GG : (ptrdiff_t)GG;
    float* obase = out + (size_t)b * FF * TT;

    if (g < 128) hs[g] = 0.f;
    __syncthreads();

    float h_reg = 0.f;
    float xt = __ldg(xp); xp += stepX;
    float x1 = __ldg(xp); xp += stepX;
    int tpre = tfirst + 2 * sgn;          // t index xp currently points at

    const ulonglong2* hv2 = (const ulonglong2*)hs;

    #pragma unroll 1
    for (int ib = 0; ib < nBlk; ib++) {
        int blk = dir ? (blk0 - ib) : (blk0 + ib);
        #pragma unroll 2
        for (int s = 0; s < 32; s++) {
            float x2 = 0.f;
            if ((unsigned)tpre < (unsigned)TT) x2 = __ldg(xp);
            xp += stepX; tpre += sgn;

            unsigned long long a0 = 0, a1 = 0, a2 = 0, a3 = 0;
            #pragma unroll
            for (int k = 0; k < 32; k += 2) {
                ulonglong2 p = hv2[k];
                ulonglong2 q = hv2[k + 1];
                a0 = ffma2(w[2 * k + 0], p.x, a0);
                a1 = ffma2(w[2 * k + 1], p.y, a1);
                a2 = ffma2(w[2 * k + 2], q.x, a2);
                a3 = ffma2(w[2 * k + 3], q.y, a3);
            }
            a0 = fadd2(a0, a1); a2 = fadd2(a2, a3); a0 = fadd2(a0, a2);
            float pre = lo32(a0) + hi32(a0) + bh;

            if (g < 256) gate[g] = fsig(xt + pre);   // r (g<128) / z (128..255)
            __syncthreads();                          // BAR1
            if (g >= 256) {
                int j = g - 256;
                float r = gate[j];
                float z = gate[128 + j];
                float n = ftanh_(xt + r * pre);      // pre == gn for this row
                h_reg = n + z * (h_reg - n);         // (1-z)*n + z*h
                hs[j] = h_reg;
                h_buf[j][s] = h_reg;
            }
            __syncthreads();                          // BAR2
            xt = x1; x1 = x2;
        }

        bool core = dir ? (blk < B1) : (blk >= B0);
        if (core) {
            int tb = dir ? (32 * blk + 31) : (32 * blk);
            for (int f = wid; f < 128; f += 12) {
                float v = h_buf[f][lane];
                atomicAdd(obase + (size_t)f * TT + tb + sgn * lane, v);
            }
        }
    }
}

// ---------------- launch ----------------
extern "C" void kernel_launch(void* const* d_in, const int* in_sizes, int n_in,
                              void* d_out, int out_size) {
    const float* x    = (const float*)d_in[0];
    const float* kern = (const float*)d_in[1];
    const float* kw   = (const float*)d_in[2];
    const float* pa   = (const float*)d_in[3];
    const float* Wihf = (const float*)d_in[4];
    const float* Whhf = (const float*)d_in[5];
    const float* bihf = (const float*)d_in[6];
    const float* bhhf = (const float*)d_in[7];
    const float* Wihb = (const float*)d_in[8];
    const float* Whhb = (const float*)d_in[9];
    const float* bihb = (const float*)d_in[10];
    const float* bhhb = (const float*)d_in[11];
    float* out = (float*)d_out;

    const int smem_bytes = 4 * 128 * ASTR * (int)sizeof(__nv_bfloat16); // 139264
    cudaFuncSetAttribute(gemm_mma_kernel,
                         cudaFuncAttributeMaxDynamicSharedMemorySize, smem_bytes);

    cudaMemsetAsync(out, 0, (size_t)out_size * sizeof(float));
    conv_prelu_kernel<<<BB * FF, 256>>>(x, kern, kw, pa);
    convW_kernel<<<3, 256>>>(Wihf, Wihb);
    gemm_mma_kernel<<<1000, 256, smem_bytes>>>(bihf, bihb);
    gru_kernel<<<NCHUNK * 2 * BB, 384>>>(Whhf, bhhf, Whhb, bhhb, out);
}